// round 15
// baseline (speedup 1.0000x reference)
#include <cuda_runtime.h>
#include <cuda_fp16.h>
#include <mma.h>
#include <cstdint>

using namespace nvcuda;

// ---------------------------------------------------------------------------
// Scratch (__device__ globals; allocation-free rule)
// ---------------------------------------------------------------------------
__device__ __align__(16) __half g_t1h[48 * 65536];       // [i][b*256+c], i<40 valid
__device__ __align__(16) __half g_t2h[40 * 768 * 256];   // [i*768+slot][c] (compact slots)
__device__ __align__(16) __half g_f1h[768 * 256];        // [j][b]
__device__ __align__(16) __half g_f2h[768 * 256];        // [h][c]
__device__ int g_map[30720];                             // id -> compact row (i*768+slot)
__device__ int g_uniq[40 * 768];                         // [i*768+slot] -> j
__device__ int g_cnt[40];                                // unique count per i

__device__ __forceinline__ void cp16(void* s, const void* g) {
    unsigned int sa = (unsigned int)__cvta_generic_to_shared(s);
    asm volatile("cp.async.cg.shared.global [%0], [%1], 16;\n" :: "r"(sa), "l"(g));
}
#define CP_COMMIT() asm volatile("cp.async.commit_group;\n" ::: "memory")
#define CP_WAIT1()  asm volatile("cp.async.wait_group 1;\n" ::: "memory")
#define CP_WAIT0()  asm volatile("cp.async.wait_group 0;\n" ::: "memory")

// ---------------------------------------------------------------------------
// k_prep: f1, f2 -> fp16
// ---------------------------------------------------------------------------
__global__ void k_prep(const float* __restrict__ f1, const float* __restrict__ f2) {
    int idx = blockIdx.x * blockDim.x + threadIdx.x;   // 0..49151 (x4 floats)
    float4 v = ((const float4*)f1)[idx];
    __half2 a = __floats2half2_rn(v.x, v.y), b = __floats2half2_rn(v.z, v.w);
    ((__half2*)g_f1h)[idx * 2] = a; ((__half2*)g_f1h)[idx * 2 + 1] = b;
    v = ((const float4*)f2)[idx];
    a = __floats2half2_rn(v.x, v.y); b = __floats2half2_rn(v.z, v.w);
    ((__half2*)g_f2h)[idx * 2] = a; ((__half2*)g_f2h)[idx * 2 + 1] = b;
}

// ---------------------------------------------------------------------------
// k_init: map <- -1, cnt <- 0  (must run every launch: deterministic restart)
// grid 120 x 256
// ---------------------------------------------------------------------------
__global__ void k_init() {
    int t = blockIdx.x * blockDim.x + threadIdx.x;
    if (t < 30720) g_map[t] = -1;
    if (t < 40) g_cnt[t] = 0;
}

// ---------------------------------------------------------------------------
// k_claim: first thread to claim an id assigns it a compact slot in segment i.
// grid 32 x 256 (8192 threads)
// ---------------------------------------------------------------------------
__global__ void k_claim(const int* __restrict__ ids) {
    int t = blockIdx.x * blockDim.x + threadIdx.x;
    int id = ids[t];
    int old = atomicCAS(&g_map[id], -1, -2);
    if (old == -1) {
        int i = id / 768, j = id - i * 768;
        int s = atomicAdd(&g_cnt[i], 1);
        g_uniq[i * 768 + s] = j;
        g_map[id] = i * 768 + s;
    }
}

// ---------------------------------------------------------------------------
// k_t1 (fp16 wmma): t1(40x65536) = f0(40x40) @ core_flat(40x65536)
// M pad 40->48, K pad 40->48. Core staged fp32->fp16 in smem (single read).
// ---------------------------------------------------------------------------
__global__ void k_t1(const float* __restrict__ core, const float* __restrict__ f0) {
    __shared__ __align__(16) __half As[48][56];    // [m][k] ld=56
    __shared__ __align__(16) __half Bs[48][136];   // [k][n] ld=136
    __shared__ float scratch[4][256];

    const int tid = threadIdx.x;                   // 128
    const int warpId = tid >> 5, lid = tid & 31;
    const int n0 = blockIdx.x * 128;

    for (int x = tid; x < 48 * 56; x += 128) (&As[0][0])[x] = __float2half(0.0f);
    for (int x = tid; x < 8 * 136; x += 128) Bs[40 + x / 136][x % 136] = __float2half(0.0f);
    __syncthreads();

    for (int x = tid; x < 1600; x += 128)
        As[x / 40][x % 40] = __float2half(f0[x]);
    for (int x = tid; x < 1280; x += 128) {
        int r = x >> 5, c4 = (x & 31) * 4;
        float4 v = *(const float4*)&core[(size_t)r * 65536 + n0 + c4];
        Bs[r][c4 + 0] = __float2half(v.x);
        Bs[r][c4 + 1] = __float2half(v.y);
        Bs[r][c4 + 2] = __float2half(v.z);
        Bs[r][c4 + 3] = __float2half(v.w);
    }
    __syncthreads();

    wmma::fragment<wmma::accumulator, 16, 16, 16, float> c[3][2];
#pragma unroll
    for (int mt = 0; mt < 3; mt++)
#pragma unroll
        for (int f = 0; f < 2; f++) wmma::fill_fragment(c[mt][f], 0.0f);

#pragma unroll
    for (int kk = 0; kk < 48; kk += 16) {
        wmma::fragment<wmma::matrix_a, 16, 16, 16, __half, wmma::row_major> a[3];
#pragma unroll
        for (int mt = 0; mt < 3; mt++)
            wmma::load_matrix_sync(a[mt], &As[mt * 16][kk], 56);
#pragma unroll
        for (int f = 0; f < 2; f++) {
            wmma::fragment<wmma::matrix_b, 16, 16, 16, __half, wmma::row_major> b;
            wmma::load_matrix_sync(b, &Bs[kk][warpId * 32 + f * 16], 136);
#pragma unroll
            for (int mt = 0; mt < 3; mt++) wmma::mma_sync(c[mt][f], a[mt], b, c[mt][f]);
        }
    }

    float* scr = scratch[warpId];
    const int lr = lid >> 1, lc = (lid & 1) * 8;
#pragma unroll
    for (int mt = 0; mt < 3; mt++)
#pragma unroll
        for (int f = 0; f < 2; f++) {
            wmma::store_matrix_sync(scr, c[mt][f], 16, wmma::mem_row_major);
            __syncwarp();
            const float* src = scr + lr * 16 + lc;
            __half2 h[4];
#pragma unroll
            for (int q = 0; q < 4; q++)
                h[q] = __floats2half2_rn(src[2 * q], src[2 * q + 1]);
            *(uint4*)&g_t1h[(size_t)(mt * 16 + lr) * 65536 + n0 + warpId * 32 + f * 16 + lc] =
                *(uint4*)&h[0];
            __syncwarp();
        }
}

// ---------------------------------------------------------------------------
// k_t2c (fp16 wmma, gathered A, compact rows only):
// t2h[i*768+s][c] = sum_b f1h[uniq[i*768+s]][b] * t1h_i[b][c]
// grid (2 n-tiles, 6 m-tiles, 40 i); CTA exits if its m-tile >= cnt[i].
// BM=128, BN=128, BK=32; 8 warps 2(M)x4(N), warp tile 64x32.
// ---------------------------------------------------------------------------
__global__ void k_t2c() {
    const int n0 = blockIdx.x * 128;
    const int m0 = blockIdx.y * 128;
    const int i  = blockIdx.z;
    const int cnt = g_cnt[i];
    if (m0 >= cnt) return;

    const __half* __restrict__ B = g_t1h + (size_t)i * 65536;
    __half* __restrict__ C = g_t2h + (size_t)i * (768 * 256);

    __shared__ __align__(16) __half As[2][128][40];    // [m][k] ld=40
    __shared__ __align__(16) __half Bs[2][32][136];    // [k][n] ld=136
    __shared__ int srow[128];

    const int tid    = threadIdx.x;
    const int warpId = tid >> 5;
    const int wm     = warpId & 1;
    const int wn     = warpId >> 1;

    if (tid < 128)
        srow[tid] = (m0 + tid < cnt) ? g_uniq[i * 768 + m0 + tid] : 0;
    __syncthreads();

    wmma::fragment<wmma::accumulator, 16, 16, 16, float> c[4][2];
#pragma unroll
    for (int r = 0; r < 4; r++)
#pragma unroll
        for (int f = 0; f < 2; f++) wmma::fill_fragment(c[r][f], 0.0f);

#define STAGE_T2C(bufi, k0)                                                             \
    do {                                                                                \
        _Pragma("unroll")                                                               \
        for (int rep = 0; rep < 2; rep++) {                                             \
            int idx = tid + rep * 256;                                                  \
            int r_ = idx >> 2, c_ = (idx & 3) * 8;                                      \
            cp16(&As[bufi][r_][c_], &g_f1h[(size_t)srow[r_] * 256 + (k0) + c_]);        \
        }                                                                               \
        _Pragma("unroll")                                                               \
        for (int rep = 0; rep < 2; rep++) {                                             \
            int idx = tid + rep * 256;                                                  \
            int r_ = idx >> 4, c_ = (idx & 15) * 8;                                     \
            cp16(&Bs[bufi][r_][c_], &B[(size_t)((k0) + r_) * 256 + n0 + c_]);           \
        }                                                                               \
        CP_COMMIT();                                                                    \
    } while (0)

    STAGE_T2C(0, 0);

    for (int it = 0; it < 8; ++it) {
        const int buf = it & 1;
        if (it < 7) { STAGE_T2C(buf ^ 1, (it + 1) * 32); CP_WAIT1(); }
        else        { CP_WAIT0(); }
        __syncthreads();

#pragma unroll
        for (int kk = 0; kk < 32; kk += 16) {
            wmma::fragment<wmma::matrix_a, 16, 16, 16, __half, wmma::row_major> a[4];
#pragma unroll
            for (int r = 0; r < 4; r++)
                wmma::load_matrix_sync(a[r], &As[buf][wm * 64 + r * 16][kk], 40);
#pragma unroll
            for (int f = 0; f < 2; f++) {
                wmma::fragment<wmma::matrix_b, 16, 16, 16, __half, wmma::row_major> b;
                wmma::load_matrix_sync(b, &Bs[buf][kk][wn * 32 + f * 16], 136);
#pragma unroll
                for (int r = 0; r < 4; r++) wmma::mma_sync(c[r][f], a[r], b, c[r][f]);
            }
        }
        __syncthreads();
    }

    // Epilogue: fp32 -> fp16 via per-warp smem staging (reuse As)
    __syncthreads();
    float* scratch = reinterpret_cast<float*>(&As[0][0][0]) + warpId * 256;
    const int lid = tid & 31;
    const int lr  = lid >> 1;
    const int lc  = (lid & 1) * 8;
#pragma unroll
    for (int r = 0; r < 4; r++)
#pragma unroll
        for (int f = 0; f < 2; f++) {
            wmma::store_matrix_sync(scratch, c[r][f], 16, wmma::mem_row_major);
            __syncwarp();
            const float* src = scratch + lr * 16 + lc;
            __half2 h[4];
#pragma unroll
            for (int q = 0; q < 4; q++)
                h[q] = __floats2half2_rn(src[2 * q], src[2 * q + 1]);
            const size_t row = (size_t)(m0 + wm * 64 + r * 16 + lr);
            *(uint4*)&C[row * 256 + n0 + wn * 32 + f * 16 + lc] = *(uint4*)&h[0];
            __syncwarp();
        }
}

// ---------------------------------------------------------------------------
// k_out (fp16 wmma, gathered via compact map): out[n][h] = t2h[map[ids[n]]] . f2h[h]
// BM=128, BN=128, BK=32. Warp tile 64x32. Output fp32 direct.
// ---------------------------------------------------------------------------
__global__ void k_out(const int* __restrict__ ids, float* __restrict__ out) {
    const int n0 = blockIdx.x * 128;
    const int m0 = blockIdx.y * 128;

    __shared__ __align__(16) __half As[2][128][40];    // [m][k] ld=40
    __shared__ __align__(16) __half Bs[2][128][40];    // [n][k] ld=40
    __shared__ int srow[128];

    const int tid    = threadIdx.x;
    const int warpId = tid >> 5;
    const int wm     = warpId & 1;
    const int wn     = warpId >> 1;

    if (tid < 128) srow[tid] = g_map[ids[m0 + tid]];
    __syncthreads();

    wmma::fragment<wmma::accumulator, 16, 16, 16, float> c[4][2];
#pragma unroll
    for (int r = 0; r < 4; r++)
#pragma unroll
        for (int f = 0; f < 2; f++) wmma::fill_fragment(c[r][f], 0.0f);

#define STAGE_OUT(bufi, k0)                                                             \
    do {                                                                                \
        _Pragma("unroll")                                                               \
        for (int rep = 0; rep < 2; rep++) {                                             \
            int idx = tid + rep * 256;                                                  \
            int r_ = idx >> 2, c_ = (idx & 3) * 8;                                      \
            cp16(&As[bufi][r_][c_], &g_t2h[(size_t)srow[r_] * 256 + (k0) + c_]);        \
        }                                                                               \
        _Pragma("unroll")                                                               \
        for (int rep = 0; rep < 2; rep++) {                                             \
            int idx = tid + rep * 256;                                                  \
            int r_ = idx >> 2, c_ = (idx & 3) * 8;                                      \
            cp16(&Bs[bufi][r_][c_], &g_f2h[(size_t)(n0 + r_) * 256 + (k0) + c_]);       \
        }                                                                               \
        CP_COMMIT();                                                                    \
    } while (0)

    STAGE_OUT(0, 0);

    for (int it = 0; it < 8; ++it) {
        const int buf = it & 1;
        if (it < 7) { STAGE_OUT(buf ^ 1, (it + 1) * 32); CP_WAIT1(); }
        else        { CP_WAIT0(); }
        __syncthreads();

#pragma unroll
        for (int kk = 0; kk < 32; kk += 16) {
            wmma::fragment<wmma::matrix_a, 16, 16, 16, __half, wmma::row_major> a[4];
#pragma unroll
            for (int r = 0; r < 4; r++)
                wmma::load_matrix_sync(a[r], &As[buf][wm * 64 + r * 16][kk], 40);
#pragma unroll
            for (int f = 0; f < 2; f++) {
                wmma::fragment<wmma::matrix_b, 16, 16, 16, __half, wmma::col_major> b;
                wmma::load_matrix_sync(b, &Bs[buf][wn * 32 + f * 16][kk], 40);
#pragma unroll
                for (int r = 0; r < 4; r++) wmma::mma_sync(c[r][f], a[r], b, c[r][f]);
            }
        }
        __syncthreads();
    }

#pragma unroll
    for (int r = 0; r < 4; r++)
#pragma unroll
        for (int f = 0; f < 2; f++)
            wmma::store_matrix_sync(
                &out[(size_t)(m0 + wm * 64 + r * 16) * 768 + n0 + wn * 32 + f * 16],
                c[r][f], 768, wmma::mem_row_major);
}

// ---------------------------------------------------------------------------
// Inputs: 0=x (unused), 1=ids, 2=core, 3=f0, 4=f1, 5=f2 ; out: 8192x768 fp32
// ---------------------------------------------------------------------------
extern "C" void kernel_launch(void* const* d_in, const int* in_sizes, int n_in,
                              void* d_out, int out_size) {
    const int*   ids  = (const int*)d_in[1];
    const float* core = (const float*)d_in[2];
    const float* f0   = (const float*)d_in[3];
    const float* f1   = (const float*)d_in[4];
    const float* f2   = (const float*)d_in[5];
    float*       out  = (float*)d_out;

    k_prep<<<192, 256>>>(f1, f2);
    k_init<<<120, 256>>>();
    k_claim<<<32, 256>>>(ids);
    k_t1<<<512, 128>>>(core, f0);
    {
        dim3 grid(2, 6, 40);                   // (n-tiles, m-tile capacity, i)
        k_t2c<<<grid, 256>>>();
    }
    {
        dim3 grid(768 / 128, 8192 / 128);      // (n-tiles, m-tiles)
        k_out<<<grid, 256>>>(ids, out);
    }
}

// round 16
// speedup vs baseline: 1.2936x; 1.2936x over previous
#include <cuda_runtime.h>
#include <cuda_fp16.h>
#include <mma.h>
#include <cstdint>

using namespace nvcuda;

// ---------------------------------------------------------------------------
// Scratch (__device__ globals; allocation-free rule) — all fp16
// g_t1h padded to 48 rows (wmma M-pad 40->48 writes 8 garbage rows; k_t2 reads
// only rows 0..39 per slab at i*65536).
// ---------------------------------------------------------------------------
__device__ __align__(16) __half g_t1h[48 * 65536];       // [i][b*256+c], i<40 valid
__device__ __align__(16) __half g_t2h[40 * 768 * 256];   // [(i*768+j)][c]
__device__ __align__(16) __half g_f1h[768 * 256];        // [j][b]
__device__ __align__(16) __half g_f2h[768 * 256];        // [h][c]

__device__ __forceinline__ void cp16(void* s, const void* g) {
    unsigned int sa = (unsigned int)__cvta_generic_to_shared(s);
    asm volatile("cp.async.cg.shared.global [%0], [%1], 16;\n" :: "r"(sa), "l"(g));
}
#define CP_COMMIT() asm volatile("cp.async.commit_group;\n" ::: "memory")
#define CP_WAIT1()  asm volatile("cp.async.wait_group 1;\n" ::: "memory")
#define CP_WAIT0()  asm volatile("cp.async.wait_group 0;\n" ::: "memory")

// ---------------------------------------------------------------------------
// k_prep: f1, f2 -> fp16
// ---------------------------------------------------------------------------
__global__ void k_prep(const float* __restrict__ f1, const float* __restrict__ f2) {
    int idx = blockIdx.x * blockDim.x + threadIdx.x;   // 0..49151 (x4 floats)
    float4 v = ((const float4*)f1)[idx];
    __half2 a = __floats2half2_rn(v.x, v.y), b = __floats2half2_rn(v.z, v.w);
    ((__half2*)g_f1h)[idx * 2] = a; ((__half2*)g_f1h)[idx * 2 + 1] = b;
    v = ((const float4*)f2)[idx];
    a = __floats2half2_rn(v.x, v.y); b = __floats2half2_rn(v.z, v.w);
    ((__half2*)g_f2h)[idx * 2] = a; ((__half2*)g_f2h)[idx * 2 + 1] = b;
}

// ---------------------------------------------------------------------------
// k_t1 (fp16 wmma, cp.async staged): t1(40x65536) = f0(40x40) @ core(40x65536)
// N-tile 64 -> 1024 CTAs (occupancy); core tile staged fp32 via cp.async (high
// MLP, no reg dependency), converted to fp16 in smem. M pad 40->48, K pad 40->48.
// 128 threads; 4 warps each own a 16-wide n-frag x 3 m-tiles.
// ---------------------------------------------------------------------------
__global__ void k_t1(const float* __restrict__ core, const float* __restrict__ f0) {
    __shared__ __align__(16) __half As[48][56];    // [m][k] ld=56 (f0, padded)
    __shared__ __align__(16) __half Bs[48][72];    // [k][n] ld=72 (core fp16, padded)
    __shared__ __align__(16) float  sc[40][64];    // staged core tile fp32
    __shared__ float scratch[4][256];

    const int tid = threadIdx.x;                   // 128
    const int warpId = tid >> 5, lid = tid & 31;
    const int n0 = blockIdx.x * 64;

    // stage core tile via cp.async: 40 rows x 256B = 640 16B chunks, 5/thread
#pragma unroll
    for (int k = 0; k < 5; k++) {
        int ci = tid + k * 128;                    // 0..639
        int r = ci >> 4, c4 = (ci & 15) * 4;
        cp16(&sc[r][c4], &core[(size_t)r * 65536 + n0 + c4]);
    }
    CP_COMMIT();

    // while loads fly: zero pads, stage f0
    for (int x = tid; x < 48 * 56; x += 128) (&As[0][0])[x] = __float2half(0.0f);
    for (int x = tid; x < 8 * 72; x += 128) Bs[40 + x / 72][x % 72] = __float2half(0.0f);
    for (int x = tid; x < 1600; x += 128) As[x / 40][x % 40] = __float2half(f0[x]);

    CP_WAIT0();
    __syncthreads();

    // convert core tile fp32 -> fp16
#pragma unroll
    for (int k = 0; k < 5; k++) {
        int ci = tid + k * 128;
        int r = ci >> 4, c4 = (ci & 15) * 4;
        float4 v = *(const float4*)&sc[r][c4];
        *(__half2*)&Bs[r][c4]     = __floats2half2_rn(v.x, v.y);
        *(__half2*)&Bs[r][c4 + 2] = __floats2half2_rn(v.z, v.w);
    }
    __syncthreads();

    wmma::fragment<wmma::accumulator, 16, 16, 16, float> c[3];
#pragma unroll
    for (int mt = 0; mt < 3; mt++) wmma::fill_fragment(c[mt], 0.0f);

#pragma unroll
    for (int kk = 0; kk < 48; kk += 16) {
        wmma::fragment<wmma::matrix_b, 16, 16, 16, __half, wmma::row_major> b;
        wmma::load_matrix_sync(b, &Bs[kk][warpId * 16], 72);
#pragma unroll
        for (int mt = 0; mt < 3; mt++) {
            wmma::fragment<wmma::matrix_a, 16, 16, 16, __half, wmma::row_major> a;
            wmma::load_matrix_sync(a, &As[mt * 16][kk], 56);
            wmma::mma_sync(c[mt], a, b, c[mt]);
        }
    }

    // epilogue: fp32 frag -> fp16; rows 40..47 land in g_t1h pad rows
    float* scr = scratch[warpId];
    const int lr = lid >> 1, lc = (lid & 1) * 8;
#pragma unroll
    for (int mt = 0; mt < 3; mt++) {
        wmma::store_matrix_sync(scr, c[mt], 16, wmma::mem_row_major);
        __syncwarp();
        const float* src = scr + lr * 16 + lc;
        __half2 h[4];
#pragma unroll
        for (int q = 0; q < 4; q++)
            h[q] = __floats2half2_rn(src[2 * q], src[2 * q + 1]);
        *(uint4*)&g_t1h[(size_t)(mt * 16 + lr) * 65536 + n0 + warpId * 16 + lc] =
            *(uint4*)&h[0];
        __syncwarp();
    }
}

// ---------------------------------------------------------------------------
// k_t2 (fp16 wmma, cp.async pipelined): per i: t2_i (768x256) = f1 @ t1_i
// A = f1h (m,k) row-major; B = t1h_i (k,n) row-major. Output fp16.
// BM=128, BN=128, BK=32. 8 warps as 2(M) x 4(N); warp tile 64x32 (c[4][2]).
// ---------------------------------------------------------------------------
__global__ void k_t2() {
    const int n0 = blockIdx.x * 128;
    const int m0 = blockIdx.y * 128;
    const int i  = blockIdx.z;

    const __half* __restrict__ A = g_f1h;
    const __half* __restrict__ B = g_t1h + (size_t)i * 65536;
    __half* __restrict__ C = g_t2h + (size_t)i * (768 * 256);

    __shared__ __align__(16) __half As[2][128][40];    // [m][k] ld=40
    __shared__ __align__(16) __half Bs[2][32][136];    // [k][n] ld=136

    const int tid    = threadIdx.x;
    const int warpId = tid >> 5;
    const int wm     = warpId & 1;       // 0..1 -> m offset wm*64
    const int wn     = warpId >> 1;      // 0..3 -> n offset wn*32

    wmma::fragment<wmma::accumulator, 16, 16, 16, float> c[4][2];
#pragma unroll
    for (int r = 0; r < 4; r++)
#pragma unroll
        for (int f = 0; f < 2; f++) wmma::fill_fragment(c[r][f], 0.0f);

#define STAGE_T2(bufi, k0)                                                              \
    do {                                                                                \
        _Pragma("unroll")                                                               \
        for (int rep = 0; rep < 2; rep++) {                                             \
            int idx = tid + rep * 256;                                                  \
            int r_ = idx >> 2, c_ = (idx & 3) * 8;                                      \
            cp16(&As[bufi][r_][c_], &A[(size_t)(m0 + r_) * 256 + (k0) + c_]);           \
        }                                                                               \
        _Pragma("unroll")                                                               \
        for (int rep = 0; rep < 2; rep++) {                                             \
            int idx = tid + rep * 256;                                                  \
            int r_ = idx >> 4, c_ = (idx & 15) * 8;                                     \
            cp16(&Bs[bufi][r_][c_], &B[(size_t)((k0) + r_) * 256 + n0 + c_]);           \
        }                                                                               \
        CP_COMMIT();                                                                    \
    } while (0)

    STAGE_T2(0, 0);

    for (int it = 0; it < 8; ++it) {
        const int buf = it & 1;
        if (it < 7) { STAGE_T2(buf ^ 1, (it + 1) * 32); CP_WAIT1(); }
        else        { CP_WAIT0(); }
        __syncthreads();

#pragma unroll
        for (int kk = 0; kk < 32; kk += 16) {
            wmma::fragment<wmma::matrix_a, 16, 16, 16, __half, wmma::row_major> a[4];
#pragma unroll
            for (int r = 0; r < 4; r++)
                wmma::load_matrix_sync(a[r], &As[buf][wm * 64 + r * 16][kk], 40);
#pragma unroll
            for (int f = 0; f < 2; f++) {
                wmma::fragment<wmma::matrix_b, 16, 16, 16, __half, wmma::row_major> b;
                wmma::load_matrix_sync(b, &Bs[buf][kk][wn * 32 + f * 16], 136);
#pragma unroll
                for (int r = 0; r < 4; r++) wmma::mma_sync(c[r][f], a[r], b, c[r][f]);
            }
        }
        __syncthreads();
    }

    // Epilogue: per-frag smem staging (reuse As as float scratch), fp32 -> fp16
    __syncthreads();
    float* scratch = reinterpret_cast<float*>(&As[0][0][0]) + warpId * 256;
    const int lid = tid & 31;
    const int lr  = lid >> 1;
    const int lc  = (lid & 1) * 8;
#pragma unroll
    for (int r = 0; r < 4; r++)
#pragma unroll
        for (int f = 0; f < 2; f++) {
            wmma::store_matrix_sync(scratch, c[r][f], 16, wmma::mem_row_major);
            __syncwarp();
            const float* src = scratch + lr * 16 + lc;
            __half2 h[4];
#pragma unroll
            for (int q = 0; q < 4; q++)
                h[q] = __floats2half2_rn(src[2 * q], src[2 * q + 1]);
            const size_t row = (size_t)(m0 + wm * 64 + r * 16 + lr);
            *(uint4*)&C[row * 256 + n0 + wn * 32 + f * 16 + lc] = *(uint4*)&h[0];
            __syncwarp();
        }
}

// ---------------------------------------------------------------------------
// k_out (fp16 wmma, gathered): out[n][h] = sum_c t2h[ids[n]][c] * f2h[h][c]
// A = gathered t2h rows (m,k) row-major; B = f2h (n,k) -> col_major fragment.
// BM=128, BN=128, BK=32. Warp tile 64x32. Output fp32 direct.
// ---------------------------------------------------------------------------
__global__ void k_out(const int* __restrict__ ids, float* __restrict__ out) {
    const int n0 = blockIdx.x * 128;
    const int m0 = blockIdx.y * 128;

    __shared__ __align__(16) __half As[2][128][40];    // [m][k] ld=40
    __shared__ __align__(16) __half Bs[2][128][40];    // [n][k] ld=40
    __shared__ int srow[128];

    const int tid    = threadIdx.x;
    const int warpId = tid >> 5;
    const int wm     = warpId & 1;
    const int wn     = warpId >> 1;

    if (tid < 128) srow[tid] = ids[m0 + tid];
    __syncthreads();

    wmma::fragment<wmma::accumulator, 16, 16, 16, float> c[4][2];
#pragma unroll
    for (int r = 0; r < 4; r++)
#pragma unroll
        for (int f = 0; f < 2; f++) wmma::fill_fragment(c[r][f], 0.0f);

#define STAGE_OUT(bufi, k0)                                                             \
    do {                                                                                \
        _Pragma("unroll")                                                               \
        for (int rep = 0; rep < 2; rep++) {                                             \
            int idx = tid + rep * 256;                                                  \
            int r_ = idx >> 2, c_ = (idx & 3) * 8;                                      \
            cp16(&As[bufi][r_][c_], &g_t2h[(size_t)srow[r_] * 256 + (k0) + c_]);        \
        }                                                                               \
        _Pragma("unroll")                                                               \
        for (int rep = 0; rep < 2; rep++) {                                             \
            int idx = tid + rep * 256;                                                  \
            int r_ = idx >> 2, c_ = (idx & 3) * 8;                                      \
            cp16(&Bs[bufi][r_][c_], &g_f2h[(size_t)(n0 + r_) * 256 + (k0) + c_]);       \
        }                                                                               \
        CP_COMMIT();                                                                    \
    } while (0)

    STAGE_OUT(0, 0);

    for (int it = 0; it < 8; ++it) {
        const int buf = it & 1;
        if (it < 7) { STAGE_OUT(buf ^ 1, (it + 1) * 32); CP_WAIT1(); }
        else        { CP_WAIT0(); }
        __syncthreads();

#pragma unroll
        for (int kk = 0; kk < 32; kk += 16) {
            wmma::fragment<wmma::matrix_a, 16, 16, 16, __half, wmma::row_major> a[4];
#pragma unroll
            for (int r = 0; r < 4; r++)
                wmma::load_matrix_sync(a[r], &As[buf][wm * 64 + r * 16][kk], 40);
#pragma unroll
            for (int f = 0; f < 2; f++) {
                // col_major: element (k, n_local) at base[n_local*ld + k]
                wmma::fragment<wmma::matrix_b, 16, 16, 16, __half, wmma::col_major> b;
                wmma::load_matrix_sync(b, &Bs[buf][wn * 32 + f * 16][kk], 40);
#pragma unroll
                for (int r = 0; r < 4; r++) wmma::mma_sync(c[r][f], a[r], b, c[r][f]);
            }
        }
        __syncthreads();
    }

#pragma unroll
    for (int r = 0; r < 4; r++)
#pragma unroll
        for (int f = 0; f < 2; f++)
            wmma::store_matrix_sync(
                &out[(size_t)(m0 + wm * 64 + r * 16) * 768 + n0 + wn * 32 + f * 16],
                c[r][f], 768, wmma::mem_row_major);
}

// ---------------------------------------------------------------------------
// Inputs: 0=x (unused), 1=ids, 2=core, 3=f0, 4=f1, 5=f2 ; out: 8192x768 fp32
// ---------------------------------------------------------------------------
extern "C" void kernel_launch(void* const* d_in, const int* in_sizes, int n_in,
                              void* d_out, int out_size) {
    const int*   ids  = (const int*)d_in[1];
    const float* core = (const float*)d_in[2];
    const float* f0   = (const float*)d_in[3];
    const float* f1   = (const float*)d_in[4];
    const float* f2   = (const float*)d_in[5];
    float*       out  = (float*)d_out;

    k_prep<<<192, 256>>>(f1, f2);
    k_t1<<<1024, 128>>>(core, f0);             // 1024 n-tiles of 64
    {
        dim3 grid(256 / 128, 768 / 128, 40);   // (n-tiles, m-tiles, i)
        k_t2<<<grid, 256>>>();
    }
    {
        dim3 grid(768 / 128, 8192 / 128);      // (n-tiles, m-tiles)
        k_out<<<grid, 256>>>(ids, out);
    }
}